// round 8
// baseline (speedup 1.0000x reference)
#include <cuda_runtime.h>
#include <cuda_bf16.h>
#include <cstdint>

#define SEQ    512
#define BATCH  64
#define DIM    512
#define MAXLEN 512
#define NWORDS (SEQ/32)

#define UTILE   64            // u rows per CTA
#define KCHUNK  32            // fp32 k elems per chunk -> 128B row (32 hi | 32 lo bf16)
#define NCHUNKS (DIM/KCHUNK)  // 16
#define KSTEPS  2             // two k=16 MMA steps per chunk

#define STAGE_BYTES 73728     // A: 64*128 = 8KB, B: 512*128 = 64KB
#define SMB_OFF     8192
#define NSTAGES     3
#define SM_TOTAL    (NSTAGES*STAGE_BYTES)   // 221184

// ---- persistent device scratch ----
// gMc: [b][ck][s][128B] ; gWc: [ck][u][128B] ; row = 64B hi | 64B lo
__device__ uint4 gMc[BATCH * NCHUNKS * SEQ * 8];   // 64 MB
__device__ uint4 gWc[NCHUNKS * MAXLEN * 8];        // 1 MB
__device__ unsigned g_maskbits[BATCH * MAXLEN * NWORDS];

__global__ void clear_mask_kernel() {
    int i = blockIdx.x * blockDim.x + threadIdx.x;
    if (i < BATCH * MAXLEN * NWORDS) g_maskbits[i] = 0u;
}

__global__ void build_mask_kernel(const int* __restrict__ eb,
                                  const int* __restrict__ eu,
                                  const int* __restrict__ ev, int E) {
    int i = blockIdx.x * blockDim.x + threadIdx.x;
    if (i >= E) return;
    atomicOr(&g_maskbits[(eb[i] * MAXLEN + eu[i]) * NWORDS + (ev[i] >> 5)],
             1u << (ev[i] & 31));
}

// split fp32 float4 -> 4 hi bf16 + 4 lo bf16 packed as uint2 each
__device__ __forceinline__ void split4(float4 v, uint2& hi, uint2& lo) {
    __nv_bfloat16 hx = __float2bfloat16_rn(v.x);
    __nv_bfloat16 hy = __float2bfloat16_rn(v.y);
    __nv_bfloat16 hz = __float2bfloat16_rn(v.z);
    __nv_bfloat16 hw = __float2bfloat16_rn(v.w);
    __nv_bfloat16 lx = __float2bfloat16_rn(v.x - __bfloat162float(hx));
    __nv_bfloat16 ly = __float2bfloat16_rn(v.y - __bfloat162float(hy));
    __nv_bfloat16 lz = __float2bfloat16_rn(v.z - __bfloat162float(hz));
    __nv_bfloat16 lw = __float2bfloat16_rn(v.w - __bfloat162float(hw));
    __nv_bfloat162 h01 = __halves2bfloat162(hx, hy), h23 = __halves2bfloat162(hz, hw);
    __nv_bfloat162 l01 = __halves2bfloat162(lx, ly), l23 = __halves2bfloat162(lz, lw);
    hi.x = *(uint32_t*)&h01; hi.y = *(uint32_t*)&h23;
    lo.x = *(uint32_t*)&l01; lo.y = *(uint32_t*)&l23;
}

// Preconvert M: (SEQ,BATCH,DIM) fp32 -> gMc [b][ck][s][32hi|32lo]
__global__ void conv_M_kernel(const float* __restrict__ Mm) {
    int i = blockIdx.x * blockDim.x + threadIdx.x;
    if (i >= BATCH * NCHUNKS * SEQ * 8) return;
    int f4 = i & 7, s = (i >> 3) & 511, ck = (i >> 12) & 15, b = i >> 16;
    float4 v = *(const float4*)&Mm[((size_t)s * BATCH + b) * DIM + ck * KCHUNK + f4 * 4];
    uint2 hi, lo; split4(v, hi, lo);
    char* base = (char*)gMc + ((size_t)((b * NCHUNKS + ck) * SEQ + s)) * 128;
    *(uint2*)(base + f4 * 8)      = hi;
    *(uint2*)(base + 64 + f4 * 8) = lo;
}

// Preconvert W: (MAXLEN,DIM) fp32 -> gWc [ck][u][32hi|32lo]
__global__ void conv_W_kernel(const float* __restrict__ Wm) {
    int i = blockIdx.x * blockDim.x + threadIdx.x;
    if (i >= NCHUNKS * MAXLEN * 8) return;
    int f4 = i & 7, u = (i >> 3) & 511, ck = i >> 12;
    float4 v = *(const float4*)&Wm[(size_t)u * DIM + ck * KCHUNK + f4 * 4];
    uint2 hi, lo; split4(v, hi, lo);
    char* base = (char*)gWc + ((size_t)(ck * MAXLEN + u)) * 128;
    *(uint2*)(base + f4 * 8)      = hi;
    *(uint2*)(base + 64 + f4 * 8) = lo;
}

// ---------------- helpers ----------------
__device__ __forceinline__ uint32_t smem_u32(const void* p) {
    uint32_t a;
    asm("{ .reg .u64 t; cvta.to.shared.u64 t, %1; cvt.u32.u64 %0, t; }" : "=r"(a) : "l"(p));
    return a;
}
__device__ __forceinline__ uint32_t sw128(uint32_t off) { return off ^ ((off >> 3) & 0x70); }

__device__ __forceinline__ void ldsm_x4(uint32_t& r0, uint32_t& r1,
                                        uint32_t& r2, uint32_t& r3, uint32_t addr) {
    asm volatile("ldmatrix.sync.aligned.m8n8.x4.shared.b16 {%0,%1,%2,%3}, [%4];"
                 : "=r"(r0), "=r"(r1), "=r"(r2), "=r"(r3) : "r"(addr));
}

__device__ __forceinline__ void mma16816(float* d, const uint32_t* a,
                                         uint32_t b0, uint32_t b1) {
    asm volatile("mma.sync.aligned.m16n8k16.row.col.f32.bf16.bf16.f32 "
                 "{%0,%1,%2,%3}, {%4,%5,%6,%7}, {%8,%9}, {%0,%1,%2,%3};"
                 : "+f"(d[0]), "+f"(d[1]), "+f"(d[2]), "+f"(d[3])
                 : "r"(a[0]), "r"(a[1]), "r"(a[2]), "r"(a[3]), "r"(b0), "r"(b1));
}

__device__ __forceinline__ void cp16(uint32_t dst, const void* src) {
    asm volatile("cp.async.cg.shared.global [%0], [%1], 16;" :: "r"(dst), "l"(src));
}

#define NTHREADS 256

__device__ __forceinline__ void load_stage(uint32_t sb, int stage, int ck,
                                           int b, int utile, int tid) {
    const uint32_t sbase = sb + stage * STAGE_BYTES;
    const char* srcB = (const char*)gMc + ((size_t)((b * NCHUNKS + ck) * SEQ)) * 128;
    #pragma unroll
    for (int it = 0; it < 16; it++) {
        int idx = it * NTHREADS + tid;
        int s = idx >> 3, f4 = idx & 7;
        cp16(sbase + SMB_OFF + sw128((uint32_t)(s * 128 + f4 * 16)),
             srcB + s * 128 + f4 * 16);
    }
    #pragma unroll
    for (int it = 0; it < 2; it++) {
        int idx = it * NTHREADS + tid;
        int u = idx >> 3, f4 = idx & 7;
        cp16(sbase + sw128((uint32_t)(u * 128 + f4 * 16)),
             (const char*)gWc + ((size_t)(ck * MAXLEN + utile + u)) * 128 + f4 * 16);
    }
    asm volatile("cp.async.commit_group;");
}

__global__ __launch_bounds__(NTHREADS, 1)
void mea_mma_kernel(float* __restrict__ out) {    // (BATCH, MAXLEN, SEQ)
    extern __shared__ char smem[];
    const uint32_t sb = smem_u32(smem);
    const int tid  = threadIdx.x;
    const int wid  = tid >> 5;
    const int lane = tid & 31;
    const int wu   = wid >> 2;      // 0..1 : u-slice (32 rows)
    const int ws   = wid & 3;       // 0..3 : s-slice (128 cols)
    const int b     = blockIdx.y;
    const int utile = blockIdx.x * UTILE;

    // ldmatrix per-lane address components (SW128, 128B rows)
    const int xr     = (lane & 7) << 4;
    const int a_kh   = (lane >> 4) * 16;
    const int b_rowl = ((lane >> 4) << 3) + (lane & 7);
    const int b_kh   = ((lane >> 3) & 1) << 4;
    const uint32_t aRowPart0 = (uint32_t)((wu * 32 + (lane & 15)) * 128);
    const uint32_t aRowPart1 = aRowPart0 + 16 * 128;
    const uint32_t bRowPart  = (uint32_t)(SMB_OFF + (ws * 128 + b_rowl) * 128);

    float acc0[16][4], acc1[16][4];   // row-groups 0 (u+0..15) and 1 (u+16..31)
    #pragma unroll
    for (int nt = 0; nt < 16; nt++)
        #pragma unroll
        for (int j = 0; j < 4; j++) { acc0[nt][j] = 0.f; acc1[nt][j] = 0.f; }

    load_stage(sb, 0, 0, b, utile, tid);
    load_stage(sb, 1, 1, b, utile, tid);

    #pragma unroll 1
    for (int ck = 0; ck < NCHUNKS; ck++) {
        if (ck == NCHUNKS - 1) asm volatile("cp.async.wait_group 0;" ::: "memory");
        else                   asm volatile("cp.async.wait_group 1;" ::: "memory");
        __syncthreads();
        if (ck + 2 < NCHUNKS)
            load_stage(sb, (ck + 2) % NSTAGES, ck + 2, b, utile, tid);

        const uint32_t sbase = sb + (ck % NSTAGES) * STAGE_BYTES;
        const uint32_t aBase0 = sbase + aRowPart0;
        const uint32_t aBase1 = sbase + aRowPart1;
        const uint32_t bBase  = sbase + bRowPart;

        #pragma unroll
        for (int ks = 0; ks < KSTEPS; ks++) {
            const uint32_t ac = (uint32_t)(ks * 32 + a_kh);
            const uint32_t bc = (uint32_t)(ks * 32 + b_kh);
            uint32_t ah0[4], ah1[4], al0[4], al1[4];
            ldsm_x4(ah0[0], ah0[1], ah0[2], ah0[3], aBase0 + (ac ^ xr));
            ldsm_x4(ah1[0], ah1[1], ah1[2], ah1[3], aBase1 + (ac ^ xr));
            ldsm_x4(al0[0], al0[1], al0[2], al0[3], aBase0 + ((ac + 64) ^ xr));
            ldsm_x4(al1[0], al1[1], al1[2], al1[3], aBase1 + ((ac + 64) ^ xr));
            #pragma unroll
            for (int np = 0; np < 8; np++) {
                uint32_t b0, b1, b2, b3;
                ldsm_x4(b0, b1, b2, b3, bBase + np * 2048 + (bc ^ xr));
                mma16816(acc0[2*np+0], ah0, b0, b1);
                mma16816(acc0[2*np+1], ah0, b2, b3);
                mma16816(acc1[2*np+0], ah1, b0, b1);
                mma16816(acc1[2*np+1], ah1, b2, b3);
                mma16816(acc0[2*np+0], al0, b0, b1);
                mma16816(acc0[2*np+1], al0, b2, b3);
                mma16816(acc1[2*np+0], al1, b0, b1);
                mma16816(acc1[2*np+1], al1, b2, b3);
                ldsm_x4(b0, b1, b2, b3, bBase + np * 2048 + ((bc + 64) ^ xr));
                mma16816(acc0[2*np+0], ah0, b0, b1);
                mma16816(acc0[2*np+1], ah0, b2, b3);
                mma16816(acc1[2*np+0], ah1, b0, b1);
                mma16816(acc1[2*np+1], ah1, b2, b3);
            }
        }
    }
    __syncthreads();   // protect smem reuse by the reduction below

    // ---------------- epilogue ----------------
    const int rl0 = lane >> 2;
    const int tig = lane & 3;
    float* red = (float*)smem;   // z: [0,256), am: [256,512)

    #pragma unroll
    for (int rg = 0; rg < 2; rg++) {
        float (*acc)[4] = rg ? acc1 : acc0;
        const int ul0 = wu * 32 + rg * 16 + rl0;
        const int ul1 = ul0 + 8;
        const int r0  = b * MAXLEN + utile + ul0;
        const int r1  = b * MAXLEN + utile + ul1;

        unsigned w0[4], w1[4];
        #pragma unroll
        for (int q = 0; q < 4; q++) {
            w0[q] = g_maskbits[r0 * NWORDS + ws * 4 + q];
            w1[q] = g_maskbits[r1 * NWORDS + ws * 4 + q];
        }

        float z0 = 0.f, am0 = 0.f, z1 = 0.f, am1 = 0.f;
        #pragma unroll
        for (int nt = 0; nt < 16; nt++) {
            const int q   = nt >> 2;
            const int bit = (nt & 3) * 8 + 2 * tig;
            float e0 = __expf(acc[nt][0]);
            float e1 = __expf(acc[nt][1]);
            float e2 = __expf(acc[nt][2]);
            float e3 = __expf(acc[nt][3]);
            acc[nt][0] = e0; acc[nt][1] = e1; acc[nt][2] = e2; acc[nt][3] = e3;
            z0 += e0 + e1; z1 += e2 + e3;
            if ((w0[q] >> bit)       & 1u) am0 += e0;
            if ((w0[q] >> (bit + 1)) & 1u) am0 += e1;
            if ((w1[q] >> bit)       & 1u) am1 += e2;
            if ((w1[q] >> (bit + 1)) & 1u) am1 += e3;
        }
        #pragma unroll
        for (int o = 1; o <= 2; o <<= 1) {
            z0  += __shfl_xor_sync(0xffffffffu, z0,  o);
            am0 += __shfl_xor_sync(0xffffffffu, am0, o);
            z1  += __shfl_xor_sync(0xffffffffu, z1,  o);
            am1 += __shfl_xor_sync(0xffffffffu, am1, o);
        }

        if (rg) __syncthreads();   // reuse red buffer between row-groups
        if (tig == 0) {
            red[ws * 64 + ul0]       = z0;
            red[ws * 64 + ul1]       = z1;
            red[256 + ws * 64 + ul0] = am0;
            red[256 + ws * 64 + ul1] = am1;
        }
        __syncthreads();
        float zs0 = 0.f, as0 = 0.f, zs1 = 0.f, as1 = 0.f;
        #pragma unroll
        for (int w = 0; w < 4; w++) {
            zs0 += red[w * 64 + ul0];       as0 += red[256 + w * 64 + ul0];
            zs1 += red[w * 64 + ul1];       as1 += red[256 + w * 64 + ul1];
        }
        const float inv0 = 1.0f / (as0 + 1e-10f * (zs0 - as0));
        const float inv1 = 1.0f / (as1 + 1e-10f * (zs1 - as1));

        #pragma unroll
        for (int nt = 0; nt < 16; nt++) {
            const int q   = nt >> 2;
            const int bit = (nt & 3) * 8 + 2 * tig;
            const int sc  = ws * 128 + nt * 8 + 2 * tig;
            float2 v0, v1;
            v0.x = ((w0[q] >> bit)       & 1u) ? acc[nt][0] * inv0 : 0.f;
            v0.y = ((w0[q] >> (bit + 1)) & 1u) ? acc[nt][1] * inv0 : 0.f;
            v1.x = ((w1[q] >> bit)       & 1u) ? acc[nt][2] * inv1 : 0.f;
            v1.y = ((w1[q] >> (bit + 1)) & 1u) ? acc[nt][3] * inv1 : 0.f;
            *(float2*)&out[(size_t)r0 * SEQ + sc] = v0;
            *(float2*)&out[(size_t)r1 * SEQ + sc] = v1;
        }
    }
}

extern "C" void kernel_launch(void* const* d_in, const int* in_sizes, int n_in,
                              void* d_out, int out_size) {
    const float* M  = (const float*)d_in[0];
    const float* W  = (const float*)d_in[1];
    const int*   eb = (const int*)d_in[3];
    const int*   eu = (const int*)d_in[4];
    const int*   ev = (const int*)d_in[5];
    const int    E  = in_sizes[3];
    float* out = (float*)d_out;

    cudaFuncSetAttribute(mea_mma_kernel,
                         cudaFuncAttributeMaxDynamicSharedMemorySize, SM_TOTAL);

    const int maskWords = BATCH * MAXLEN * NWORDS;
    clear_mask_kernel<<<(maskWords + 255) / 256, 256>>>();
    build_mask_kernel<<<(E + 255) / 256, 256>>>(eb, eu, ev, E);
    conv_M_kernel<<<(BATCH * NCHUNKS * SEQ * 8) / 256, 256>>>(M);
    conv_W_kernel<<<(NCHUNKS * MAXLEN * 8) / 256, 256>>>(W);
    mea_mma_kernel<<<dim3(MAXLEN / UTILE, BATCH), NTHREADS, SM_TOTAL>>>(out);
}

// round 9
// speedup vs baseline: 1.3976x; 1.3976x over previous
#include <cuda_runtime.h>
#include <cuda_fp16.h>
#include <cstdint>

#define SEQ    512
#define BATCH  64
#define DIM    512
#define MAXLEN 512
#define NWORDS (SEQ/32)

#define UTILE   64            // u rows per CTA
#define KCHUNK  64            // fp32 k elems per chunk -> 128B fp16 row
#define NCHUNKS (DIM/KCHUNK)  // 8
#define KSTEPS  4             // four k=16 MMA steps per chunk

// ---- stage layout (bytes) ----
#define SM_A_HI   0                       // 64 rows x 128B = 8 KB
#define SM_A_LO   8192                    // 8 KB
#define SM_B      16384                   // 512 rows x 128B = 64 KB
#define STAGE_BYTES 81920
#define NSTAGES   2
#define SM_TOTAL  (NSTAGES*STAGE_BYTES)   // 163840

#define NTHREADS 256

// ---- persistent device scratch ----
// gMc: [b][ck][s][128B fp16] ; gWhi/gWlo: [ck][u][128B fp16]
__device__ uint4 gMc [BATCH * NCHUNKS * SEQ * 8];   // 32 MB
__device__ uint4 gWhi[NCHUNKS * MAXLEN * 8];        // 512 KB
__device__ uint4 gWlo[NCHUNKS * MAXLEN * 8];        // 512 KB
__device__ unsigned g_maskbits[BATCH * MAXLEN * NWORDS];

__global__ void clear_mask_kernel() {
    int i = blockIdx.x * blockDim.x + threadIdx.x;
    if (i < BATCH * MAXLEN * NWORDS) g_maskbits[i] = 0u;
}

__global__ void build_mask_kernel(const int* __restrict__ eb,
                                  const int* __restrict__ eu,
                                  const int* __restrict__ ev, int E) {
    int i = blockIdx.x * blockDim.x + threadIdx.x;
    if (i >= E) return;
    atomicOr(&g_maskbits[(eb[i] * MAXLEN + eu[i]) * NWORDS + (ev[i] >> 5)],
             1u << (ev[i] & 31));
}

// Preconvert M: (SEQ,BATCH,DIM) fp32 -> gMc fp16 rows (single precision pass)
__global__ void conv_M_kernel(const float* __restrict__ Mm) {
    int i = blockIdx.x * blockDim.x + threadIdx.x;
    if (i >= BATCH * NCHUNKS * SEQ * 8) return;
    int f8 = i & 7, s = (i >> 3) & 511, ck = (i >> 12) & 7, b = i >> 15;
    const float* src = &Mm[((size_t)s * BATCH + b) * DIM + ck * KCHUNK + f8 * 8];
    float4 v0 = *(const float4*)src;
    float4 v1 = *(const float4*)(src + 4);
    __half2 h0 = __floats2half2_rn(v0.x, v0.y);
    __half2 h1 = __floats2half2_rn(v0.z, v0.w);
    __half2 h2 = __floats2half2_rn(v1.x, v1.y);
    __half2 h3 = __floats2half2_rn(v1.z, v1.w);
    uint4 o; o.x = *(uint32_t*)&h0; o.y = *(uint32_t*)&h1;
             o.z = *(uint32_t*)&h2; o.w = *(uint32_t*)&h3;
    *(uint4*)((char*)gMc + ((size_t)((b * NCHUNKS + ck) * SEQ + s)) * 128 + f8 * 16) = o;
}

// Preconvert W: fp32 -> fp16 hi + fp16 lo (residual) rows
__global__ void conv_W_kernel(const float* __restrict__ Wm) {
    int i = blockIdx.x * blockDim.x + threadIdx.x;
    if (i >= NCHUNKS * MAXLEN * 8) return;
    int f8 = i & 7, u = (i >> 3) & 511, ck = i >> 12;
    const float* src = &Wm[(size_t)u * DIM + ck * KCHUNK + f8 * 8];
    float f[8];
    *(float4*)&f[0] = *(const float4*)src;
    *(float4*)&f[4] = *(const float4*)(src + 4);
    __half hi[8], lo[8];
    #pragma unroll
    for (int j = 0; j < 8; j++) {
        hi[j] = __float2half_rn(f[j]);
        lo[j] = __float2half_rn(f[j] - __half2float(hi[j]));
    }
    uint4 oh = *(uint4*)hi, ol = *(uint4*)lo;
    size_t off = ((size_t)(ck * MAXLEN + u)) * 128 + f8 * 16;
    *(uint4*)((char*)gWhi + off) = oh;
    *(uint4*)((char*)gWlo + off) = ol;
}

// ---------------- helpers ----------------
__device__ __forceinline__ uint32_t smem_u32(const void* p) {
    uint32_t a;
    asm("{ .reg .u64 t; cvta.to.shared.u64 t, %1; cvt.u32.u64 %0, t; }" : "=r"(a) : "l"(p));
    return a;
}
__device__ __forceinline__ uint32_t sw128(uint32_t off) { return off ^ ((off >> 3) & 0x70); }

__device__ __forceinline__ void ldsm_x4(uint32_t& r0, uint32_t& r1,
                                        uint32_t& r2, uint32_t& r3, uint32_t addr) {
    asm volatile("ldmatrix.sync.aligned.m8n8.x4.shared.b16 {%0,%1,%2,%3}, [%4];"
                 : "=r"(r0), "=r"(r1), "=r"(r2), "=r"(r3) : "r"(addr));
}

__device__ __forceinline__ void mma16816(float* d, const uint32_t* a,
                                         uint32_t b0, uint32_t b1) {
    asm volatile("mma.sync.aligned.m16n8k16.row.col.f32.f16.f16.f32 "
                 "{%0,%1,%2,%3}, {%4,%5,%6,%7}, {%8,%9}, {%0,%1,%2,%3};"
                 : "+f"(d[0]), "+f"(d[1]), "+f"(d[2]), "+f"(d[3])
                 : "r"(a[0]), "r"(a[1]), "r"(a[2]), "r"(a[3]), "r"(b0), "r"(b1));
}

__device__ __forceinline__ void cp16(uint32_t dst, const void* src) {
    asm volatile("cp.async.cg.shared.global [%0], [%1], 16;" :: "r"(dst), "l"(src));
}

__device__ __forceinline__ void load_stage(uint32_t sb, int stage, int ck,
                                           int b, int utile, int tid) {
    const uint32_t sbase = sb + stage * STAGE_BYTES;
    const char* srcB = (const char*)gMc + ((size_t)((b * NCHUNKS + ck) * SEQ)) * 128;
    #pragma unroll
    for (int it = 0; it < 16; it++) {
        int idx = it * NTHREADS + tid;
        int s = idx >> 3, f4 = idx & 7;
        cp16(sbase + SM_B + sw128((uint32_t)(s * 128 + f4 * 16)),
             srcB + s * 128 + f4 * 16);
    }
    #pragma unroll
    for (int it = 0; it < 2; it++) {
        int idx = it * NTHREADS + tid;
        int u = idx >> 3, f4 = idx & 7;
        size_t goff = ((size_t)(ck * MAXLEN + utile + u)) * 128 + f4 * 16;
        uint32_t soff = sw128((uint32_t)(u * 128 + f4 * 16));
        cp16(sbase + SM_A_HI + soff, (const char*)gWhi + goff);
        cp16(sbase + SM_A_LO + soff, (const char*)gWlo + goff);
    }
    asm volatile("cp.async.commit_group;");
}

__global__ __launch_bounds__(NTHREADS, 1)
void mea_mma_kernel(float* __restrict__ out) {    // (BATCH, MAXLEN, SEQ)
    extern __shared__ char smem[];
    const uint32_t sb = smem_u32(smem);
    const int tid  = threadIdx.x;
    const int wid  = tid >> 5;
    const int lane = tid & 31;
    const int wu   = wid >> 2;      // 0..1 : u-slice (32 rows)
    const int ws   = wid & 3;       // 0..3 : s-slice (128 cols)
    const int b     = blockIdx.y;
    const int utile = blockIdx.x * UTILE;

    // ldmatrix per-lane address components (SW128, 128B rows)
    const int xr     = (lane & 7) << 4;
    const int a_kh   = (lane >> 4) * 16;
    const int b_rowl = ((lane >> 4) << 3) + (lane & 7);
    const int b_kh   = ((lane >> 3) & 1) << 4;
    const uint32_t aRow0 = (uint32_t)((wu * 32 + (lane & 15)) * 128);
    const uint32_t aRow1 = aRow0 + 16 * 128;
    const uint32_t bRow  = (uint32_t)(SM_B + (ws * 128 + b_rowl) * 128);

    float acc0[16][4], acc1[16][4];   // row-groups (u+0..15) and (u+16..31)
    #pragma unroll
    for (int nt = 0; nt < 16; nt++)
        #pragma unroll
        for (int j = 0; j < 4; j++) { acc0[nt][j] = 0.f; acc1[nt][j] = 0.f; }

    load_stage(sb, 0, 0, b, utile, tid);

    #pragma unroll 1
    for (int ck = 0; ck < NCHUNKS; ck++) {
        asm volatile("cp.async.wait_group 0;" ::: "memory");
        __syncthreads();
        if (ck + 1 < NCHUNKS)
            load_stage(sb, (ck + 1) & 1, ck + 1, b, utile, tid);

        const uint32_t sbase = sb + (ck & 1) * STAGE_BYTES;
        const uint32_t aHi0 = sbase + SM_A_HI + aRow0;
        const uint32_t aHi1 = sbase + SM_A_HI + aRow1;
        const uint32_t aLo0 = sbase + SM_A_LO + aRow0;
        const uint32_t aLo1 = sbase + SM_A_LO + aRow1;
        const uint32_t bB   = sbase + bRow;

        #pragma unroll
        for (int ks = 0; ks < KSTEPS; ks++) {
            const uint32_t ac = (uint32_t)((ks * 32 + a_kh) ^ xr);
            const uint32_t bc = (uint32_t)((ks * 32 + b_kh) ^ xr);
            uint32_t ah0[4], ah1[4], al0[4], al1[4];
            ldsm_x4(ah0[0], ah0[1], ah0[2], ah0[3], aHi0 + ac);
            ldsm_x4(ah1[0], ah1[1], ah1[2], ah1[3], aHi1 + ac);
            ldsm_x4(al0[0], al0[1], al0[2], al0[3], aLo0 + ac);
            ldsm_x4(al1[0], al1[1], al1[2], al1[3], aLo1 + ac);
            #pragma unroll
            for (int np = 0; np < 8; np++) {
                uint32_t b0, b1, b2, b3;
                ldsm_x4(b0, b1, b2, b3, bB + np * 2048 + bc);
                mma16816(acc0[2*np+0], ah0, b0, b1);
                mma16816(acc0[2*np+1], ah0, b2, b3);
                mma16816(acc1[2*np+0], ah1, b0, b1);
                mma16816(acc1[2*np+1], ah1, b2, b3);
                mma16816(acc0[2*np+0], al0, b0, b1);
                mma16816(acc0[2*np+1], al0, b2, b3);
                mma16816(acc1[2*np+0], al1, b0, b1);
                mma16816(acc1[2*np+1], al1, b2, b3);
            }
        }
    }
    __syncthreads();   // protect smem reuse by the reduction below

    // ---------------- epilogue ----------------
    const int rl0 = lane >> 2;
    const int tig = lane & 3;
    float* red = (float*)smem;   // z: [0,256), am: [256,512)

    #pragma unroll
    for (int rg = 0; rg < 2; rg++) {
        float (*acc)[4] = rg ? acc1 : acc0;
        const int ul0 = wu * 32 + rg * 16 + rl0;
        const int ul1 = ul0 + 8;
        const int r0  = b * MAXLEN + utile + ul0;
        const int r1  = b * MAXLEN + utile + ul1;

        unsigned w0[4], w1[4];
        #pragma unroll
        for (int q = 0; q < 4; q++) {
            w0[q] = g_maskbits[r0 * NWORDS + ws * 4 + q];
            w1[q] = g_maskbits[r1 * NWORDS + ws * 4 + q];
        }

        float z0 = 0.f, am0 = 0.f, z1 = 0.f, am1 = 0.f;
        #pragma unroll
        for (int nt = 0; nt < 16; nt++) {
            const int q   = nt >> 2;
            const int bit = (nt & 3) * 8 + 2 * tig;
            float e0 = __expf(acc[nt][0]);
            float e1 = __expf(acc[nt][1]);
            float e2 = __expf(acc[nt][2]);
            float e3 = __expf(acc[nt][3]);
            acc[nt][0] = e0; acc[nt][1] = e1; acc[nt][2] = e2; acc[nt][3] = e3;
            z0 += e0 + e1; z1 += e2 + e3;
            if ((w0[q] >> bit)       & 1u) am0 += e0;
            if ((w0[q] >> (bit + 1)) & 1u) am0 += e1;
            if ((w1[q] >> bit)       & 1u) am1 += e2;
            if ((w1[q] >> (bit + 1)) & 1u) am1 += e3;
        }
        #pragma unroll
        for (int o = 1; o <= 2; o <<= 1) {
            z0  += __shfl_xor_sync(0xffffffffu, z0,  o);
            am0 += __shfl_xor_sync(0xffffffffu, am0, o);
            z1  += __shfl_xor_sync(0xffffffffu, z1,  o);
            am1 += __shfl_xor_sync(0xffffffffu, am1, o);
        }

        if (rg) __syncthreads();   // reuse red buffer between row-groups
        if (tig == 0) {
            red[ws * 64 + ul0]       = z0;
            red[ws * 64 + ul1]       = z1;
            red[256 + ws * 64 + ul0] = am0;
            red[256 + ws * 64 + ul1] = am1;
        }
        __syncthreads();
        float zs0 = 0.f, as0 = 0.f, zs1 = 0.f, as1 = 0.f;
        #pragma unroll
        for (int w = 0; w < 4; w++) {
            zs0 += red[w * 64 + ul0];       as0 += red[256 + w * 64 + ul0];
            zs1 += red[w * 64 + ul1];       as1 += red[256 + w * 64 + ul1];
        }
        const float inv0 = 1.0f / (as0 + 1e-10f * (zs0 - as0));
        const float inv1 = 1.0f / (as1 + 1e-10f * (zs1 - as1));

        #pragma unroll
        for (int nt = 0; nt < 16; nt++) {
            const int q   = nt >> 2;
            const int bit = (nt & 3) * 8 + 2 * tig;
            const int sc  = ws * 128 + nt * 8 + 2 * tig;
            float2 v0, v1;
            v0.x = ((w0[q] >> bit)       & 1u) ? acc[nt][0] * inv0 : 0.f;
            v0.y = ((w0[q] >> (bit + 1)) & 1u) ? acc[nt][1] * inv0 : 0.f;
            v1.x = ((w1[q] >> bit)       & 1u) ? acc[nt][2] * inv1 : 0.f;
            v1.y = ((w1[q] >> (bit + 1)) & 1u) ? acc[nt][3] * inv1 : 0.f;
            *(float2*)&out[(size_t)r0 * SEQ + sc] = v0;
            *(float2*)&out[(size_t)r1 * SEQ + sc] = v1;
        }
    }
}

extern "C" void kernel_launch(void* const* d_in, const int* in_sizes, int n_in,
                              void* d_out, int out_size) {
    const float* M  = (const float*)d_in[0];
    const float* W  = (const float*)d_in[1];
    const int*   eb = (const int*)d_in[3];
    const int*   eu = (const int*)d_in[4];
    const int*   ev = (const int*)d_in[5];
    const int    E  = in_sizes[3];
    float* out = (float*)d_out;

    cudaFuncSetAttribute(mea_mma_kernel,
                         cudaFuncAttributeMaxDynamicSharedMemorySize, SM_TOTAL);

    const int maskWords = BATCH * MAXLEN * NWORDS;
    clear_mask_kernel<<<(maskWords + 255) / 256, 256>>>();
    build_mask_kernel<<<(E + 255) / 256, 256>>>(eb, eu, ev, E);
    conv_M_kernel<<<(BATCH * NCHUNKS * SEQ * 8) / 256, 256>>>(M);
    conv_W_kernel<<<(NCHUNKS * MAXLEN * 8) / 256, 256>>>(W);
    mea_mma_kernel<<<dim3(MAXLEN / UTILE, BATCH), NTHREADS, SM_TOTAL>>>(out);
}

// round 10
// speedup vs baseline: 1.8545x; 1.3270x over previous
#include <cuda_runtime.h>
#include <cuda_fp16.h>
#include <cstdint>

#define SEQ    512
#define BATCH  64
#define DIM    512
#define MAXLEN 512
#define NWORDS (SEQ/32)

#define UTILE   64            // u rows per CTA
#define KCHUNK  64            // fp32 k elems per chunk -> 128B fp16 row
#define NCHUNKS (DIM/KCHUNK)  // 8
#define KSTEPS  4             // four k=16 MMA steps per chunk

// ---- stage layout (bytes) ----
#define SM_A      0                       // 64 rows x 128B = 8 KB
#define SM_B      8192                    // 512 rows x 128B = 64 KB
#define STAGE_BYTES 73728
#define NSTAGES   2
#define SM_TOTAL  (NSTAGES*STAGE_BYTES)   // 147456

#define NTHREADS 256

// ---- persistent device scratch ----
// gMc: [b][ck][s][128B fp16] ; gWc: [ck][u][128B fp16]
__device__ uint4 gMc[BATCH * NCHUNKS * SEQ * 8];   // 32 MB
__device__ uint4 gWc[NCHUNKS * MAXLEN * 8];        // 512 KB
__device__ unsigned g_maskbits[BATCH * MAXLEN * NWORDS];

__global__ void clear_mask_kernel() {
    int i = blockIdx.x * blockDim.x + threadIdx.x;
    if (i < BATCH * MAXLEN * NWORDS) g_maskbits[i] = 0u;
}

__global__ void build_mask_kernel(const int* __restrict__ eb,
                                  const int* __restrict__ eu,
                                  const int* __restrict__ ev, int E) {
    int i = blockIdx.x * blockDim.x + threadIdx.x;
    if (i >= E) return;
    atomicOr(&g_maskbits[(eb[i] * MAXLEN + eu[i]) * NWORDS + (ev[i] >> 5)],
             1u << (ev[i] & 31));
}

// Preconvert M: (SEQ,BATCH,DIM) fp32 -> gMc fp16 rows
__global__ void conv_M_kernel(const float* __restrict__ Mm) {
    int i = blockIdx.x * blockDim.x + threadIdx.x;
    if (i >= BATCH * NCHUNKS * SEQ * 8) return;
    int f8 = i & 7, s = (i >> 3) & 511, ck = (i >> 12) & 7, b = i >> 15;
    const float* src = &Mm[((size_t)s * BATCH + b) * DIM + ck * KCHUNK + f8 * 8];
    float4 v0 = *(const float4*)src;
    float4 v1 = *(const float4*)(src + 4);
    __half2 h0 = __floats2half2_rn(v0.x, v0.y);
    __half2 h1 = __floats2half2_rn(v0.z, v0.w);
    __half2 h2 = __floats2half2_rn(v1.x, v1.y);
    __half2 h3 = __floats2half2_rn(v1.z, v1.w);
    uint4 o; o.x = *(uint32_t*)&h0; o.y = *(uint32_t*)&h1;
             o.z = *(uint32_t*)&h2; o.w = *(uint32_t*)&h3;
    *(uint4*)((char*)gMc + ((size_t)((b * NCHUNKS + ck) * SEQ + s)) * 128 + f8 * 16) = o;
}

// Preconvert W: fp32 -> fp16 rows
__global__ void conv_W_kernel(const float* __restrict__ Wm) {
    int i = blockIdx.x * blockDim.x + threadIdx.x;
    if (i >= NCHUNKS * MAXLEN * 8) return;
    int f8 = i & 7, u = (i >> 3) & 511, ck = i >> 12;
    const float* src = &Wm[(size_t)u * DIM + ck * KCHUNK + f8 * 8];
    float4 v0 = *(const float4*)src;
    float4 v1 = *(const float4*)(src + 4);
    __half2 h0 = __floats2half2_rn(v0.x, v0.y);
    __half2 h1 = __floats2half2_rn(v0.z, v0.w);
    __half2 h2 = __floats2half2_rn(v1.x, v1.y);
    __half2 h3 = __floats2half2_rn(v1.z, v1.w);
    uint4 o; o.x = *(uint32_t*)&h0; o.y = *(uint32_t*)&h1;
             o.z = *(uint32_t*)&h2; o.w = *(uint32_t*)&h3;
    *(uint4*)((char*)gWc + ((size_t)(ck * MAXLEN + u)) * 128 + f8 * 16) = o;
}

// ---------------- helpers ----------------
__device__ __forceinline__ uint32_t smem_u32(const void* p) {
    uint32_t a;
    asm("{ .reg .u64 t; cvta.to.shared.u64 t, %1; cvt.u32.u64 %0, t; }" : "=r"(a) : "l"(p));
    return a;
}
__device__ __forceinline__ uint32_t sw128(uint32_t off) { return off ^ ((off >> 3) & 0x70); }

__device__ __forceinline__ void ldsm_x4(uint32_t& r0, uint32_t& r1,
                                        uint32_t& r2, uint32_t& r3, uint32_t addr) {
    asm volatile("ldmatrix.sync.aligned.m8n8.x4.shared.b16 {%0,%1,%2,%3}, [%4];"
                 : "=r"(r0), "=r"(r1), "=r"(r2), "=r"(r3) : "r"(addr));
}

__device__ __forceinline__ void mma16816(float* d, const uint32_t* a,
                                         uint32_t b0, uint32_t b1) {
    asm volatile("mma.sync.aligned.m16n8k16.row.col.f32.f16.f16.f32 "
                 "{%0,%1,%2,%3}, {%4,%5,%6,%7}, {%8,%9}, {%0,%1,%2,%3};"
                 : "+f"(d[0]), "+f"(d[1]), "+f"(d[2]), "+f"(d[3])
                 : "r"(a[0]), "r"(a[1]), "r"(a[2]), "r"(a[3]), "r"(b0), "r"(b1));
}

__device__ __forceinline__ void cp16(uint32_t dst, const void* src) {
    asm volatile("cp.async.cg.shared.global [%0], [%1], 16;" :: "r"(dst), "l"(src));
}

__device__ __forceinline__ void load_stage(uint32_t sb, int stage, int ck,
                                           int b, int utile, int tid) {
    const uint32_t sbase = sb + stage * STAGE_BYTES;
    const char* srcB = (const char*)gMc + ((size_t)((b * NCHUNKS + ck) * SEQ)) * 128;
    #pragma unroll
    for (int it = 0; it < 16; it++) {
        int idx = it * NTHREADS + tid;
        int s = idx >> 3, f4 = idx & 7;
        cp16(sbase + SM_B + sw128((uint32_t)(s * 128 + f4 * 16)),
             srcB + s * 128 + f4 * 16);
    }
    #pragma unroll
    for (int it = 0; it < 2; it++) {
        int idx = it * NTHREADS + tid;
        int u = idx >> 3, f4 = idx & 7;
        cp16(sbase + SM_A + sw128((uint32_t)(u * 128 + f4 * 16)),
             (const char*)gWc + ((size_t)(ck * MAXLEN + utile + u)) * 128 + f4 * 16);
    }
    asm volatile("cp.async.commit_group;");
}

__global__ __launch_bounds__(NTHREADS, 1)
void mea_mma_kernel(float* __restrict__ out) {    // (BATCH, MAXLEN, SEQ)
    extern __shared__ char smem[];
    const uint32_t sb = smem_u32(smem);
    const int tid  = threadIdx.x;
    const int wid  = tid >> 5;
    const int lane = tid & 31;
    const int wu   = wid >> 2;      // 0..1 : u-slice (32 rows)
    const int ws   = wid & 3;       // 0..3 : s-slice (128 cols)
    const int b     = blockIdx.y;
    const int utile = blockIdx.x * UTILE;

    // ldmatrix per-lane address components (SW128, 128B rows)
    const int xr     = (lane & 7) << 4;
    const int a_kh   = (lane >> 4) * 16;
    const int b_rowl = ((lane >> 4) << 3) + (lane & 7);
    const int b_kh   = ((lane >> 3) & 1) << 4;
    const uint32_t aRow0 = (uint32_t)((wu * 32 + (lane & 15)) * 128);
    const uint32_t aRow1 = aRow0 + 16 * 128;
    const uint32_t bRow  = (uint32_t)(SM_B + (ws * 128 + b_rowl) * 128);

    float acc0[16][4], acc1[16][4];   // row-groups (u+0..15) and (u+16..31)
    #pragma unroll
    for (int nt = 0; nt < 16; nt++)
        #pragma unroll
        for (int j = 0; j < 4; j++) { acc0[nt][j] = 0.f; acc1[nt][j] = 0.f; }

    load_stage(sb, 0, 0, b, utile, tid);

    #pragma unroll 1
    for (int ck = 0; ck < NCHUNKS; ck++) {
        asm volatile("cp.async.wait_group 0;" ::: "memory");
        __syncthreads();
        if (ck + 1 < NCHUNKS)
            load_stage(sb, (ck + 1) & 1, ck + 1, b, utile, tid);

        const uint32_t sbase = sb + (ck & 1) * STAGE_BYTES;
        const uint32_t aB0 = sbase + SM_A + aRow0;
        const uint32_t aB1 = sbase + SM_A + aRow1;
        const uint32_t bB  = sbase + bRow;

        #pragma unroll
        for (int ks = 0; ks < KSTEPS; ks++) {
            const uint32_t ac = (uint32_t)((ks * 32 + a_kh) ^ xr);
            const uint32_t bc = (uint32_t)((ks * 32 + b_kh) ^ xr);
            uint32_t a0[4], a1[4];
            ldsm_x4(a0[0], a0[1], a0[2], a0[3], aB0 + ac);
            ldsm_x4(a1[0], a1[1], a1[2], a1[3], aB1 + ac);
            #pragma unroll
            for (int np = 0; np < 8; np++) {
                uint32_t b0, b1, b2, b3;
                ldsm_x4(b0, b1, b2, b3, bB + np * 2048 + bc);
                mma16816(acc0[2*np+0], a0, b0, b1);
                mma16816(acc0[2*np+1], a0, b2, b3);
                mma16816(acc1[2*np+0], a1, b0, b1);
                mma16816(acc1[2*np+1], a1, b2, b3);
            }
        }
    }
    __syncthreads();   // protect smem reuse by the reduction below

    // ---------------- epilogue ----------------
    const int rl0 = lane >> 2;
    const int tig = lane & 3;
    float* red = (float*)smem;   // z: [0,256), am: [256,512)

    #pragma unroll
    for (int rg = 0; rg < 2; rg++) {
        float (*acc)[4] = rg ? acc1 : acc0;
        const int ul0 = wu * 32 + rg * 16 + rl0;
        const int ul1 = ul0 + 8;
        const int r0  = b * MAXLEN + utile + ul0;
        const int r1  = b * MAXLEN + utile + ul1;

        unsigned w0[4], w1[4];
        #pragma unroll
        for (int q = 0; q < 4; q++) {
            w0[q] = g_maskbits[r0 * NWORDS + ws * 4 + q];
            w1[q] = g_maskbits[r1 * NWORDS + ws * 4 + q];
        }

        float z0 = 0.f, am0 = 0.f, z1 = 0.f, am1 = 0.f;
        #pragma unroll
        for (int nt = 0; nt < 16; nt++) {
            const int q   = nt >> 2;
            const int bit = (nt & 3) * 8 + 2 * tig;
            float e0 = __expf(acc[nt][0]);
            float e1 = __expf(acc[nt][1]);
            float e2 = __expf(acc[nt][2]);
            float e3 = __expf(acc[nt][3]);
            acc[nt][0] = e0; acc[nt][1] = e1; acc[nt][2] = e2; acc[nt][3] = e3;
            z0 += e0 + e1; z1 += e2 + e3;
            if ((w0[q] >> bit)       & 1u) am0 += e0;
            if ((w0[q] >> (bit + 1)) & 1u) am0 += e1;
            if ((w1[q] >> bit)       & 1u) am1 += e2;
            if ((w1[q] >> (bit + 1)) & 1u) am1 += e3;
        }
        #pragma unroll
        for (int o = 1; o <= 2; o <<= 1) {
            z0  += __shfl_xor_sync(0xffffffffu, z0,  o);
            am0 += __shfl_xor_sync(0xffffffffu, am0, o);
            z1  += __shfl_xor_sync(0xffffffffu, z1,  o);
            am1 += __shfl_xor_sync(0xffffffffu, am1, o);
        }

        if (rg) __syncthreads();   // reuse red buffer between row-groups
        if (tig == 0) {
            red[ws * 64 + ul0]       = z0;
            red[ws * 64 + ul1]       = z1;
            red[256 + ws * 64 + ul0] = am0;
            red[256 + ws * 64 + ul1] = am1;
        }
        __syncthreads();
        float zs0 = 0.f, as0 = 0.f, zs1 = 0.f, as1 = 0.f;
        #pragma unroll
        for (int w = 0; w < 4; w++) {
            zs0 += red[w * 64 + ul0];       as0 += red[256 + w * 64 + ul0];
            zs1 += red[w * 64 + ul1];       as1 += red[256 + w * 64 + ul1];
        }
        const float inv0 = 1.0f / (as0 + 1e-10f * (zs0 - as0));
        const float inv1 = 1.0f / (as1 + 1e-10f * (zs1 - as1));

        #pragma unroll
        for (int nt = 0; nt < 16; nt++) {
            const int q   = nt >> 2;
            const int bit = (nt & 3) * 8 + 2 * tig;
            const int sc  = ws * 128 + nt * 8 + 2 * tig;
            float2 v0, v1;
            v0.x = ((w0[q] >> bit)       & 1u) ? acc[nt][0] * inv0 : 0.f;
            v0.y = ((w0[q] >> (bit + 1)) & 1u) ? acc[nt][1] * inv0 : 0.f;
            v1.x = ((w1[q] >> bit)       & 1u) ? acc[nt][2] * inv1 : 0.f;
            v1.y = ((w1[q] >> (bit + 1)) & 1u) ? acc[nt][3] * inv1 : 0.f;
            *(float2*)&out[(size_t)r0 * SEQ + sc] = v0;
            *(float2*)&out[(size_t)r1 * SEQ + sc] = v1;
        }
    }
}

extern "C" void kernel_launch(void* const* d_in, const int* in_sizes, int n_in,
                              void* d_out, int out_size) {
    const float* M  = (const float*)d_in[0];
    const float* W  = (const float*)d_in[1];
    const int*   eb = (const int*)d_in[3];
    const int*   eu = (const int*)d_in[4];
    const int*   ev = (const int*)d_in[5];
    const int    E  = in_sizes[3];
    float* out = (float*)d_out;

    cudaFuncSetAttribute(mea_mma_kernel,
                         cudaFuncAttributeMaxDynamicSharedMemorySize, SM_TOTAL);

    const int maskWords = BATCH * MAXLEN * NWORDS;
    clear_mask_kernel<<<(maskWords + 255) / 256, 256>>>();
    build_mask_kernel<<<(E + 255) / 256, 256>>>(eb, eu, ev, E);
    conv_M_kernel<<<(BATCH * NCHUNKS * SEQ * 8) / 256, 256>>>(M);
    conv_W_kernel<<<(NCHUNKS * MAXLEN * 8) / 256, 256>>>(W);
    mea_mma_kernel<<<dim3(MAXLEN / UTILE, BATCH), NTHREADS, SM_TOTAL>>>(out);
}

// round 11
// speedup vs baseline: 1.9440x; 1.0482x over previous
#include <cuda_runtime.h>
#include <cuda_fp16.h>
#include <cstdint>

#define SEQ    512
#define BATCH  64
#define DIM    512
#define MAXLEN 512
#define NWORDS (SEQ/32)

#define UTILE   64            // u rows per CTA
#define KCHUNK  64            // fp32 k elems per chunk -> 128B fp16 row
#define NCHUNKS (DIM/KCHUNK)  // 8
#define KSTEPS  4             // four k=16 MMA steps per chunk

// ---- stage layout (bytes) ----
#define SM_A      0                       // 64 rows x 128B = 8 KB
#define SM_B      8192                    // 512 rows x 128B = 64 KB
#define STAGE_BYTES 73728
#define NSTAGES   3
#define SM_TOTAL  (NSTAGES*STAGE_BYTES)   // 221184

#define NTHREADS 256

#define CONVM_ITEMS (BATCH * NCHUNKS * SEQ * 8)   // 262144
#define CONVW_ITEMS (NCHUNKS * MAXLEN * 8)        // 32768

// ---- persistent device scratch ----
// gMc: [b][ck][s][128B fp16] ; gWc: [ck][u][128B fp16]
__device__ uint4 gMc[BATCH * NCHUNKS * SEQ * 8];   // 32 MB
__device__ uint4 gWc[NCHUNKS * MAXLEN * 8];        // 512 KB
// Zero at module load; mea_mma's epilogue re-zeroes every word it consumes,
// so every invocation (correctness run + each graph replay) leaves it zeroed.
__device__ unsigned g_maskbits[BATCH * MAXLEN * NWORDS];

// One kernel does mask-build + conv_M + conv_W concurrently (block-partitioned;
// the three jobs touch disjoint data and the bitmap is already zero).
__global__ void prep_kernel(const int* __restrict__ eb,
                            const int* __restrict__ eu,
                            const int* __restrict__ ev, int E, int edgeBlocks,
                            const float* __restrict__ Mm,
                            const float* __restrict__ Wm) {
    const int bid = blockIdx.x;
    const int tid = threadIdx.x;

    if (bid < edgeBlocks) {                     // ---- build mask ----
        int i = bid * NTHREADS + tid;
        if (i < E)
            atomicOr(&g_maskbits[(eb[i] * MAXLEN + eu[i]) * NWORDS + (ev[i] >> 5)],
                     1u << (ev[i] & 31));
        return;
    }
    int b2 = bid - edgeBlocks;
    if (b2 < CONVM_ITEMS / NTHREADS) {          // ---- conv M -> fp16 rows ----
        int i = b2 * NTHREADS + tid;
        int f8 = i & 7, s = (i >> 3) & 511, ck = (i >> 12) & 7, b = i >> 15;
        const float* src = &Mm[((size_t)s * BATCH + b) * DIM + ck * KCHUNK + f8 * 8];
        float4 v0 = *(const float4*)src;
        float4 v1 = *(const float4*)(src + 4);
        __half2 h0 = __floats2half2_rn(v0.x, v0.y);
        __half2 h1 = __floats2half2_rn(v0.z, v0.w);
        __half2 h2 = __floats2half2_rn(v1.x, v1.y);
        __half2 h3 = __floats2half2_rn(v1.z, v1.w);
        uint4 o; o.x = *(uint32_t*)&h0; o.y = *(uint32_t*)&h1;
                 o.z = *(uint32_t*)&h2; o.w = *(uint32_t*)&h3;
        *(uint4*)((char*)gMc + ((size_t)((b * NCHUNKS + ck) * SEQ + s)) * 128 + f8 * 16) = o;
        return;
    }
    int b3 = b2 - CONVM_ITEMS / NTHREADS;       // ---- conv W -> fp16 rows ----
    {
        int i = b3 * NTHREADS + tid;
        if (i >= CONVW_ITEMS) return;
        int f8 = i & 7, u = (i >> 3) & 511, ck = i >> 12;
        const float* src = &Wm[(size_t)u * DIM + ck * KCHUNK + f8 * 8];
        float4 v0 = *(const float4*)src;
        float4 v1 = *(const float4*)(src + 4);
        __half2 h0 = __floats2half2_rn(v0.x, v0.y);
        __half2 h1 = __floats2half2_rn(v0.z, v0.w);
        __half2 h2 = __floats2half2_rn(v1.x, v1.y);
        __half2 h3 = __floats2half2_rn(v1.z, v1.w);
        uint4 o; o.x = *(uint32_t*)&h0; o.y = *(uint32_t*)&h1;
                 o.z = *(uint32_t*)&h2; o.w = *(uint32_t*)&h3;
        *(uint4*)((char*)gWc + ((size_t)(ck * MAXLEN + u)) * 128 + f8 * 16) = o;
    }
}

// ---------------- helpers ----------------
__device__ __forceinline__ uint32_t smem_u32(const void* p) {
    uint32_t a;
    asm("{ .reg .u64 t; cvta.to.shared.u64 t, %1; cvt.u32.u64 %0, t; }" : "=r"(a) : "l"(p));
    return a;
}
__device__ __forceinline__ uint32_t sw128(uint32_t off) { return off ^ ((off >> 3) & 0x70); }

__device__ __forceinline__ void ldsm_x4(uint32_t& r0, uint32_t& r1,
                                        uint32_t& r2, uint32_t& r3, uint32_t addr) {
    asm volatile("ldmatrix.sync.aligned.m8n8.x4.shared.b16 {%0,%1,%2,%3}, [%4];"
                 : "=r"(r0), "=r"(r1), "=r"(r2), "=r"(r3) : "r"(addr));
}

__device__ __forceinline__ void mma16816(float* d, const uint32_t* a,
                                         uint32_t b0, uint32_t b1) {
    asm volatile("mma.sync.aligned.m16n8k16.row.col.f32.f16.f16.f32 "
                 "{%0,%1,%2,%3}, {%4,%5,%6,%7}, {%8,%9}, {%0,%1,%2,%3};"
                 : "+f"(d[0]), "+f"(d[1]), "+f"(d[2]), "+f"(d[3])
                 : "r"(a[0]), "r"(a[1]), "r"(a[2]), "r"(a[3]), "r"(b0), "r"(b1));
}

__device__ __forceinline__ void cp16(uint32_t dst, const void* src) {
    asm volatile("cp.async.cg.shared.global [%0], [%1], 16;" :: "r"(dst), "l"(src));
}

__device__ __forceinline__ void load_stage(uint32_t sb, int stage, int ck,
                                           int b, int utile, int tid) {
    const uint32_t sbase = sb + stage * STAGE_BYTES;
    const char* srcB = (const char*)gMc + ((size_t)((b * NCHUNKS + ck) * SEQ)) * 128;
    #pragma unroll
    for (int it = 0; it < 16; it++) {
        int idx = it * NTHREADS + tid;
        int s = idx >> 3, f4 = idx & 7;
        cp16(sbase + SM_B + sw128((uint32_t)(s * 128 + f4 * 16)),
             srcB + s * 128 + f4 * 16);
    }
    #pragma unroll
    for (int it = 0; it < 2; it++) {
        int idx = it * NTHREADS + tid;
        int u = idx >> 3, f4 = idx & 7;
        cp16(sbase + SM_A + sw128((uint32_t)(u * 128 + f4 * 16)),
             (const char*)gWc + ((size_t)(ck * MAXLEN + utile + u)) * 128 + f4 * 16);
    }
    asm volatile("cp.async.commit_group;");
}

__global__ __launch_bounds__(NTHREADS, 1)
void mea_mma_kernel(float* __restrict__ out) {    // (BATCH, MAXLEN, SEQ)
    extern __shared__ char smem[];
    const uint32_t sb = smem_u32(smem);
    const int tid  = threadIdx.x;
    const int wid  = tid >> 5;
    const int lane = tid & 31;
    const int wu   = wid >> 2;      // 0..1 : u-slice (32 rows)
    const int ws   = wid & 3;       // 0..3 : s-slice (128 cols)
    const int b     = blockIdx.y;
    const int utile = blockIdx.x * UTILE;

    // ldmatrix per-lane address components (SW128, 128B rows)
    const int xr     = (lane & 7) << 4;
    const int a_kh   = (lane >> 4) * 16;
    const int b_rowl = ((lane >> 4) << 3) + (lane & 7);
    const int b_kh   = ((lane >> 3) & 1) << 4;
    const uint32_t aRow0 = (uint32_t)((wu * 32 + (lane & 15)) * 128);
    const uint32_t aRow1 = aRow0 + 16 * 128;
    const uint32_t bRow  = (uint32_t)(SM_B + (ws * 128 + b_rowl) * 128);

    float acc0[16][4], acc1[16][4];   // row-groups (u+0..15) and (u+16..31)
    #pragma unroll
    for (int nt = 0; nt < 16; nt++)
        #pragma unroll
        for (int j = 0; j < 4; j++) { acc0[nt][j] = 0.f; acc1[nt][j] = 0.f; }

    load_stage(sb, 0, 0, b, utile, tid);
    load_stage(sb, 1, 1, b, utile, tid);

    #pragma unroll 1
    for (int ck = 0; ck < NCHUNKS; ck++) {
        if (ck == NCHUNKS - 1) asm volatile("cp.async.wait_group 0;" ::: "memory");
        else                   asm volatile("cp.async.wait_group 1;" ::: "memory");
        __syncthreads();
        if (ck + 2 < NCHUNKS)
            load_stage(sb, (ck + 2) % NSTAGES, ck + 2, b, utile, tid);

        const uint32_t sbase = sb + (ck % NSTAGES) * STAGE_BYTES;
        const uint32_t aB0 = sbase + SM_A + aRow0;
        const uint32_t aB1 = sbase + SM_A + aRow1;
        const uint32_t bB  = sbase + bRow;

        #pragma unroll
        for (int ks = 0; ks < KSTEPS; ks++) {
            const uint32_t ac = (uint32_t)((ks * 32 + a_kh) ^ xr);
            const uint32_t bc = (uint32_t)((ks * 32 + b_kh) ^ xr);
            uint32_t a0[4], a1[4];
            ldsm_x4(a0[0], a0[1], a0[2], a0[3], aB0 + ac);
            ldsm_x4(a1[0], a1[1], a1[2], a1[3], aB1 + ac);
            #pragma unroll
            for (int np = 0; np < 8; np++) {
                uint32_t b0, b1, b2, b3;
                ldsm_x4(b0, b1, b2, b3, bB + np * 2048 + bc);
                mma16816(acc0[2*np+0], a0, b0, b1);
                mma16816(acc0[2*np+1], a0, b2, b3);
                mma16816(acc1[2*np+0], a1, b0, b1);
                mma16816(acc1[2*np+1], a1, b2, b3);
            }
        }
    }
    __syncthreads();   // protect smem reuse by the reduction below

    // ---------------- epilogue ----------------
    const int rl0 = lane >> 2;
    const int tig = lane & 3;
    float* red = (float*)smem;   // z: [0,256), am: [256,512)

    #pragma unroll
    for (int rg = 0; rg < 2; rg++) {
        float (*acc)[4] = rg ? acc1 : acc0;
        const int ul0 = wu * 32 + rg * 16 + rl0;
        const int ul1 = ul0 + 8;
        const int r0  = b * MAXLEN + utile + ul0;
        const int r1  = b * MAXLEN + utile + ul1;

        unsigned w0[4], w1[4];
        #pragma unroll
        for (int q = 0; q < 4; q++) {
            w0[q] = g_maskbits[r0 * NWORDS + ws * 4 + q];
            w1[q] = g_maskbits[r1 * NWORDS + ws * 4 + q];
        }
        // Consume-and-clear: each (row, word) is owned by exactly one warp's
        // tig==0 lane. Leaves the bitmap all-zero for the next invocation.
        if (tig == 0) {
            #pragma unroll
            for (int q = 0; q < 4; q++) {
                g_maskbits[r0 * NWORDS + ws * 4 + q] = 0u;
                g_maskbits[r1 * NWORDS + ws * 4 + q] = 0u;
            }
        }

        float z0 = 0.f, am0 = 0.f, z1 = 0.f, am1 = 0.f;
        #pragma unroll
        for (int nt = 0; nt < 16; nt++) {
            const int q   = nt >> 2;
            const int bit = (nt & 3) * 8 + 2 * tig;
            float e0 = __expf(acc[nt][0]);
            float e1 = __expf(acc[nt][1]);
            float e2 = __expf(acc[nt][2]);
            float e3 = __expf(acc[nt][3]);
            acc[nt][0] = e0; acc[nt][1] = e1; acc[nt][2] = e2; acc[nt][3] = e3;
            z0 += e0 + e1; z1 += e2 + e3;
            if ((w0[q] >> bit)       & 1u) am0 += e0;
            if ((w0[q] >> (bit + 1)) & 1u) am0 += e1;
            if ((w1[q] >> bit)       & 1u) am1 += e2;
            if ((w1[q] >> (bit + 1)) & 1u) am1 += e3;
        }
        #pragma unroll
        for (int o = 1; o <= 2; o <<= 1) {
            z0  += __shfl_xor_sync(0xffffffffu, z0,  o);
            am0 += __shfl_xor_sync(0xffffffffu, am0, o);
            z1  += __shfl_xor_sync(0xffffffffu, z1,  o);
            am1 += __shfl_xor_sync(0xffffffffu, am1, o);
        }

        if (rg) __syncthreads();   // reuse red buffer between row-groups
        if (tig == 0) {
            red[ws * 64 + ul0]       = z0;
            red[ws * 64 + ul1]       = z1;
            red[256 + ws * 64 + ul0] = am0;
            red[256 + ws * 64 + ul1] = am1;
        }
        __syncthreads();
        float zs0 = 0.f, as0 = 0.f, zs1 = 0.f, as1 = 0.f;
        #pragma unroll
        for (int w = 0; w < 4; w++) {
            zs0 += red[w * 64 + ul0];       as0 += red[256 + w * 64 + ul0];
            zs1 += red[w * 64 + ul1];       as1 += red[256 + w * 64 + ul1];
        }
        const float inv0 = 1.0f / (as0 + 1e-10f * (zs0 - as0));
        const float inv1 = 1.0f / (as1 + 1e-10f * (zs1 - as1));

        #pragma unroll
        for (int nt = 0; nt < 16; nt++) {
            const int q   = nt >> 2;
            const int bit = (nt & 3) * 8 + 2 * tig;
            const int sc  = ws * 128 + nt * 8 + 2 * tig;
            float2 v0, v1;
            v0.x = ((w0[q] >> bit)       & 1u) ? acc[nt][0] * inv0 : 0.f;
            v0.y = ((w0[q] >> (bit + 1)) & 1u) ? acc[nt][1] * inv0 : 0.f;
            v1.x = ((w1[q] >> bit)       & 1u) ? acc[nt][2] * inv1 : 0.f;
            v1.y = ((w1[q] >> (bit + 1)) & 1u) ? acc[nt][3] * inv1 : 0.f;
            *(float2*)&out[(size_t)r0 * SEQ + sc] = v0;
            *(float2*)&out[(size_t)r1 * SEQ + sc] = v1;
        }
    }
}

extern "C" void kernel_launch(void* const* d_in, const int* in_sizes, int n_in,
                              void* d_out, int out_size) {
    const float* M  = (const float*)d_in[0];
    const float* W  = (const float*)d_in[1];
    const int*   eb = (const int*)d_in[3];
    const int*   eu = (const int*)d_in[4];
    const int*   ev = (const int*)d_in[5];
    const int    E  = in_sizes[3];
    float* out = (float*)d_out;

    cudaFuncSetAttribute(mea_mma_kernel,
                         cudaFuncAttributeMaxDynamicSharedMemorySize, SM_TOTAL);

    const int edgeBlocks = (E + NTHREADS - 1) / NTHREADS;
    const int prepBlocks = edgeBlocks + CONVM_ITEMS / NTHREADS
                         + (CONVW_ITEMS + NTHREADS - 1) / NTHREADS;
    prep_kernel<<<prepBlocks, NTHREADS>>>(eb, eu, ev, E, edgeBlocks, M, W);
    mea_mma_kernel<<<dim3(MAXLEN / UTILE, BATCH), NTHREADS, SM_TOTAL>>>(out);
}